// round 6
// baseline (speedup 1.0000x reference)
#include <cuda_runtime.h>
#include <cstdint>

#define TB 64
#define TT 2048
#define TC 96
#define TS 256
#define NEGF (-1e30f)
#define LOG2E 1.4426950408889634f
#define LN2   0.6931471805599453f

#define NTH 256            // 8 warps; thread i owns states 2i, 2i+1 (+512 on t255)
#define DB  32             // boundary ring depth (steps)
#define RCH 6              // row-ring chunks (8 rows each => 48 rows)
#define NCHK (TT / 8)

__device__ float g_lse[TB * TT];   // log2-domain log-softmax denominators

__device__ __forceinline__ float ex2f_(float x) {
    float r; asm("ex2.approx.f32 %0, %1;" : "=f"(r) : "f"(x)); return r;
}
__device__ __forceinline__ float lg2f_(float x) {
    float r; asm("lg2.approx.f32 %0, %1;" : "=f"(r) : "f"(x)); return r;
}
__device__ __forceinline__ float lse2f_(float a, float b) {
    float m = fmaxf(a, b), n = fminf(a, b);
    return m + lg2f_(1.0f + ex2f_(n - m));
}
__device__ __forceinline__ float lse3f_(float a, float b, float c) {
    float s1 = fmaxf(a, b), t1 = fminf(a, b);
    float m  = fmaxf(s1, c);
    float md = fmaxf(fminf(s1, c), t1);
    float mn = fminf(t1, c);
    return m + lg2f_(1.0f + ex2f_(md - m) + ex2f_(mn - m));
}

__device__ __forceinline__ int ld_acq(const int* p) {
    int v; unsigned a = (unsigned)__cvta_generic_to_shared(p);
    asm volatile("ld.acquire.cta.shared.b32 %0, [%1];" : "=r"(v) : "r"(a) : "memory");
    return v;
}
__device__ __forceinline__ void st_rel(int* p, int v) {
    unsigned a = (unsigned)__cvta_generic_to_shared(p);
    asm volatile("st.release.cta.shared.b32 [%0], %1;" :: "r"(a), "r"(v) : "memory");
}

// ---------------------------------------------------------------------------
__global__ void lse_kernel(const float* __restrict__ x) {
    int row = blockIdx.x * 4 + (threadIdx.x >> 5);
    if (row >= TB * TT) return;
    int lane = threadIdx.x & 31;
    const float* p = x + (size_t)row * TC;
    float v0 = p[lane], v1 = p[lane + 32], v2 = p[lane + 64];
    float m = fmaxf(fmaxf(v0, v1), v2);
    #pragma unroll
    for (int o = 16; o; o >>= 1) m = fmaxf(m, __shfl_xor_sync(0xffffffffu, m, o));
    float s = ex2f_((v0 - m) * LOG2E) + ex2f_((v1 - m) * LOG2E) + ex2f_((v2 - m) * LOG2E);
    #pragma unroll
    for (int o = 16; o; o >>= 1) s += __shfl_xor_sync(0xffffffffu, s, o);
    if (lane == 0) g_lse[row] = m * LOG2E + lg2f_(s);
}

__global__ void zero_kernel(float* o) { if (threadIdx.x == 0) *o = 0.0f; }

// ---------------------------------------------------------------------------
// One CTA per batch element. Barrier-free warp-skewed alpha recursion.
// ---------------------------------------------------------------------------
__global__ void __launch_bounds__(NTH, 1) ctc_kernel(
    const float* __restrict__ x,
    const int*   __restrict__ tgt32,
    const int*   __restrict__ tmask,
    float*       __restrict__ out)
{
    __shared__ __align__(16) float rowring[RCH][8 * TC + 8];  // 8 rows + 8 lse
    __shared__ float bOdd[8][DB];      // warp-boundary odd alphas, slot = step % DB
    __shared__ int   prog[8];          // warp w completed steps (release)
    __shared__ int   rows_ready;       // highest complete chunk index (release)
    __shared__ float shE[NTH + 1];     // final even alphas (incl. state 512)
    __shared__ float shOf[NTH];        // final odd alphas
    __shared__ int   lab[TS];
    __shared__ int   tlen_sh;

    const int tid  = threadIdx.x;
    const int lane = tid & 31;
    const int w    = tid >> 5;
    const int b    = blockIdx.x;

    // int32 vs int64 target storage (labels >= 1 => high word 0 iff int64 LE)
    const bool is64 = (tgt32[1] == 0);
    const int  stride = is64 ? 2 : 1;
    lab[tid] = tgt32[((size_t)b * TS + tid) * stride];
    if (tid == 0) { tlen_sh = 0; rows_ready = -1; }
    if (tid < 8) prog[tid] = 0;
    __syncthreads();

    {
        int m = tmask[b * TS + tid];
        #pragma unroll
        for (int o = 16; o; o >>= 1) m += __shfl_xor_sync(0xffffffffu, m, o);
        if (lane == 0) atomicAdd(&tlen_sh, m);
    }

    const int  i    = tid;
    const int  cls  = lab[i];
    const bool skip = (i > 0) && (lab[i] != lab[i - 1]);

    const float* xb   = x + (size_t)b * TT * TC;
    const float* lseb = g_lse + (size_t)b * TT;

    // warp-0-only chunk prefetch: 8 rows of logits (3072B) + 8 lse (32B)
    auto issue_chunk = [&](int c) {
        unsigned sa = (unsigned)__cvta_generic_to_shared(rowring[c % RCH]);
        const float* src = xb + (size_t)c * 768;
        #pragma unroll
        for (int k = lane; k < 192; k += 32) {
            asm volatile("cp.async.ca.shared.global [%0], [%1], 16;"
                         :: "r"(sa + k * 16), "l"(src + k * 4));
        }
        if (lane < 2) {
            asm volatile("cp.async.ca.shared.global [%0], [%1], 16;"
                         :: "r"(sa + 768 * 4 + lane * 16), "l"(lseb + c * 8 + lane * 4));
        }
        asm volatile("cp.async.commit_group;");
    };

    float aE = NEGF, aO = NEGF, aE2 = NEGF;   // aE2: state 512 on thread 255

    // ---- prologue: t = 0 ----
    if (w == 0) {
        issue_chunk(0); issue_chunk(1); issue_chunk(2);
        asm volatile("cp.async.wait_group 2;");
        if (lane == 0) st_rel(&rows_ready, 0);
    } else {
        while (ld_acq(&rows_ready) < 0) {}
    }
    {
        const float* R = rowring[0];
        float lse2 = R[8 * TC];
        if (i == 0) {
            aE = fmaf(R[0],   LOG2E, -lse2);
            aO = fmaf(R[cls], LOG2E, -lse2);
        }
        if (lane == 31) {
            bOdd[w][1] = aO;
            st_rel(&prog[w], 1);
        }
    }

    // ---- main loop ----
    for (int t = 1; t < TT; ++t) {
        if ((t & 7) == 0) {
            int c = t >> 3;
            if (w == 0) {
                while (ld_acq(&prog[7]) < t - 16) {}       // ring backpressure
                if (c + 2 < NCHK) issue_chunk(c + 2);
                else asm volatile("cp.async.commit_group;");
                asm volatile("cp.async.wait_group 2;");    // chunk c complete
                if (lane == 0) st_rel(&rows_ready, c);
            } else {
                while (ld_acq(&rows_ready) < c) {}
            }
        }
        if (w > 0) {
            while (ld_acq(&prog[w - 1]) < t) {}            // producer ready
        }

        const float* Rb = rowring[(t >> 3) % RCH];
        const float* R  = Rb + (t & 7) * TC;
        float lse2 = Rb[8 * TC + (t & 7)];

        float lo = __shfl_up_sync(0xffffffffu, aO, 1);     // old left odd alpha
        if (lane == 0) lo = w ? bOdd[w - 1][t & (DB - 1)] : NEGF;

        float lpB = fmaf(R[0],   LOG2E, -lse2);
        float lpO = fmaf(R[cls], LOG2E, -lse2);

        float newE = lse2f_(aE, lo) + lpB;                 // state 2i
        float c3   = skip ? lo : NEGF;
        float newO = lse3f_(aO, aE, c3) + lpO;             // state 2i+1
        if (tid == NTH - 1)
            aE2 = lse2f_(aE2, aO) + lpB;                   // state 512
        aE = newE; aO = newO;

        if (lane == 31) {
            bOdd[w][(t + 1) & (DB - 1)] = aO;
            st_rel(&prog[w], t + 1);
        }
    }

    shE[i]  = aE;
    shOf[i] = aO;
    if (tid == NTH - 1) shE[NTH] = aE2;
    __syncthreads();

    if (tid == 0) {
        int len = tlen_sh;
        float loss = 0.0f;
        if (len >= 1 && len <= TS) {
            float la = lse2f_(shE[len], shOf[len - 1]);    // alpha[2len], alpha[2len-1]
            loss = -la * LN2;
            if (!isfinite(loss) || loss >= 1e29f) loss = 0.0f;
            loss = loss / ((float)len * (float)TB);
        }
        atomicAdd(out, loss);
    }
}

// ---------------------------------------------------------------------------
extern "C" void kernel_launch(void* const* d_in, const int* in_sizes, int n_in,
                              void* d_out, int out_size) {
    const float* x     = (const float*)d_in[0];
    const int*   tgt   = (const int*)  d_in[1];
    const int*   tmask = (const int*)  d_in[3];
    float* out = (float*)d_out;

    zero_kernel<<<1, 32>>>(out);
    lse_kernel<<<(TB * TT + 3) / 4, 128>>>(x);
    ctc_kernel<<<TB, NTH>>>(x, tgt, tmask, out);
}

// round 7
// speedup vs baseline: 1.1339x; 1.1339x over previous
#include <cuda_runtime.h>
#include <cstdint>

#define TB 64
#define TT 2048
#define TC 96
#define TS 256
#define NEGF (-1e30f)
#define LOG2E 1.4426950408889634f
#define LN2   0.6931471805599453f

#define NTH 256            // 8 warps; thread i owns states 2i, 2i+1; t255 also 512
#define GST 288            // gathered row stride (floats), 1152B = 9*128B aligned
#define CH  4              // rows per cp.async chunk
#define RCH 6              // chunks in ring
#define NCHK (TT / CH)

// gathered log2-probs: G[b][t][i] = lp2(cls_i), G[b][t][256] = lp2(blank)
__device__ float g_gather[(size_t)TB * TT * GST];

__device__ __forceinline__ float ex2f_(float x) {
    float r; asm("ex2.approx.f32 %0, %1;" : "=f"(r) : "f"(x)); return r;
}
__device__ __forceinline__ float lg2f_(float x) {
    float r; asm("lg2.approx.f32 %0, %1;" : "=f"(r) : "f"(x)); return r;
}
__device__ __forceinline__ float lse2f_(float a, float b) {
    float m = fmaxf(a, b), n = fminf(a, b);
    return m + lg2f_(1.0f + ex2f_(n - m));
}
__device__ __forceinline__ float lse3f_(float a, float b, float c) {
    float s1 = fmaxf(a, b), t1 = fminf(a, b);
    float m  = fmaxf(s1, c);
    float md = fmaxf(fminf(s1, c), t1);
    float mn = fminf(t1, c);
    return m + lg2f_(1.0f + ex2f_(md - m) + ex2f_(mn - m));
}

__global__ void zero_kernel(float* o) { if (threadIdx.x == 0) *o = 0.0f; }

// ---------------------------------------------------------------------------
// Gather kernel: fused log-softmax + per-state class gather.
// Block: 256 threads, handles 8 consecutive t rows of one batch element.
// ---------------------------------------------------------------------------
__global__ void __launch_bounds__(256) gather_kernel(
    const float* __restrict__ x,       // [B,T,C]
    const int*   __restrict__ tgt32)
{
    __shared__ int   lab[TS];
    __shared__ float rows[8][TC];

    const int tid  = threadIdx.x;
    const int lane = tid & 31;
    const int r    = tid >> 5;         // warp -> row within block
    const int b    = blockIdx.y;
    const int t0   = blockIdx.x * 8;

    // int32 vs int64 target storage (labels >= 1 => high word 0 iff int64 LE)
    const bool is64 = (tgt32[1] == 0);
    const int  stride = is64 ? 2 : 1;
    lab[tid] = tgt32[((size_t)b * TS + tid) * stride];

    const float* xr = x + ((size_t)b * TT + t0) * TC;
    for (int k = tid; k < 8 * TC; k += 256) rows[0][k] = xr[k];
    __syncthreads();

    // per-warp log-sum-exp over 96 classes (log2 domain)
    float v0 = rows[r][lane], v1 = rows[r][lane + 32], v2 = rows[r][lane + 64];
    float m = fmaxf(fmaxf(v0, v1), v2);
    #pragma unroll
    for (int o = 16; o; o >>= 1) m = fmaxf(m, __shfl_xor_sync(0xffffffffu, m, o));
    float s = ex2f_((v0 - m) * LOG2E) + ex2f_((v1 - m) * LOG2E) + ex2f_((v2 - m) * LOG2E);
    #pragma unroll
    for (int o = 16; o; o >>= 1) s += __shfl_xor_sync(0xffffffffu, s, o);
    float lse2 = fmaf(m, LOG2E, lg2f_(s));

    float* Gr = g_gather + ((size_t)b * TT + t0 + r) * GST;
    #pragma unroll
    for (int i = lane; i < TS; i += 32)
        Gr[i] = fmaf(rows[r][lab[i]], LOG2E, -lse2);
    if (lane == 0)
        Gr[TS] = fmaf(rows[r][0], LOG2E, -lse2);
}

// ---------------------------------------------------------------------------
// Main kernel: one CTA per batch element, 8 warps, alpha recursion.
// ---------------------------------------------------------------------------
__global__ void __launch_bounds__(NTH, 1) ctc_kernel(
    const int* __restrict__ tgt32,
    const int* __restrict__ tmask,
    float*     __restrict__ out)
{
    __shared__ __align__(16) float ring[RCH][CH * 260];  // 260 floats/row used
    __shared__ float shOB[2][8];       // warp-boundary odd alphas (double buf)
    __shared__ float shE[NTH + 1];
    __shared__ float shOf[NTH];
    __shared__ int   tlen_sh;

    const int tid  = threadIdx.x;
    const int lane = tid & 31;
    const int w    = tid >> 5;
    const int b    = blockIdx.x;
    const int i    = tid;

    const bool is64 = (tgt32[1] == 0);
    const int  stride = is64 ? 2 : 1;
    const int* trow = tgt32 + (size_t)b * TS * stride;
    int myLab   = trow[i * stride];
    int leftLab = (i > 0) ? trow[(i - 1) * stride] : -1;
    const bool skip = (i > 0) && (myLab != leftLab);

    if (tid == 0) tlen_sh = 0;
    if (tid < 8) { shOB[0][tid] = NEGF; shOB[1][tid] = NEGF; }
    __syncthreads();
    {
        int m = tmask[b * TS + tid];
        #pragma unroll
        for (int o = 16; o; o >>= 1) m += __shfl_xor_sync(0xffffffffu, m, o);
        if (lane == 0) atomicAdd(&tlen_sh, m);
    }

    const float* Gb = g_gather + (size_t)b * TT * GST;

    // chunk prefetch: CH rows of 260 floats each (first 257 meaningful)
    auto issue_chunk = [&](int c) {
        if (c < NCHK) {
            unsigned sa = (unsigned)__cvta_generic_to_shared(ring[c % RCH]);
            const float* src = Gb + (size_t)c * CH * GST;
            #pragma unroll
            for (int k = tid; k < CH * 65; k += NTH) {
                int row = k / 65, word = k % 65;
                asm volatile("cp.async.ca.shared.global [%0], [%1], 16;"
                             :: "r"(sa + (row * 260 + word * 4) * 4),
                                "l"(src + (size_t)row * GST + word * 4));
            }
        }
        asm volatile("cp.async.commit_group;");
    };

    issue_chunk(0); issue_chunk(1); issue_chunk(2);
    asm volatile("cp.async.wait_group 2;");

    float aE = NEGF, aO = NEGF, aE2 = NEGF;

    // ---- t = 0 ----
    {
        const float* R = ring[0];
        float lpB = R[TS];
        if (i == 0) { aE = lpB; aO = R[0]; }
        if (lane == 31) shOB[1][w] = aO;
    }

    // ---- main loop ----
    for (int t = 1; t < TT; ++t) {
        __syncthreads();
        if ((t & (CH - 1)) == 0) {
            int c = t / CH;
            issue_chunk(c + 2);
            asm volatile("cp.async.wait_group 2;");
        }

        const float* R = ring[(t / CH) % RCH] + (t & (CH - 1)) * 260;
        float lp  = R[i];
        float lpB = R[TS];

        float lo = __shfl_up_sync(0xffffffffu, aO, 1);
        if (lane == 0) lo = w ? shOB[t & 1][w - 1] : NEGF;

        float newE = lse2f_(aE, lo) + lpB;                  // state 2i (blank)
        float newO = lse3f_(aO, aE, skip ? lo : NEGF) + lp; // state 2i+1
        if (tid == NTH - 1)
            aE2 = lse2f_(aE2, aO) + lpB;                    // state 512
        aE = newE; aO = newO;

        if (lane == 31) shOB[(t + 1) & 1][w] = aO;
    }

    shE[i]  = aE;
    shOf[i] = aO;
    if (tid == NTH - 1) shE[NTH] = aE2;
    __syncthreads();

    if (tid == 0) {
        int len = tlen_sh;
        float loss = 0.0f;
        if (len >= 1 && len <= TS) {
            float la = lse2f_(shE[len], shOf[len - 1]);     // alpha[2len], alpha[2len-1]
            loss = -la * LN2;
            if (!isfinite(loss) || loss >= 1e29f) loss = 0.0f;
            loss = loss / ((float)len * (float)TB);
        }
        atomicAdd(out, loss);
    }
}

// ---------------------------------------------------------------------------
extern "C" void kernel_launch(void* const* d_in, const int* in_sizes, int n_in,
                              void* d_out, int out_size) {
    const float* x     = (const float*)d_in[0];   // predictions [B,T,C] f32
    const int*   tgt   = (const int*)  d_in[1];   // targets (int32 or int64 words)
    const int*   tmask = (const int*)  d_in[3];   // targets_mask [B,S] i32
    float* out = (float*)d_out;

    zero_kernel<<<1, 32>>>(out);
    dim3 ggrid(TT / 8, TB);
    gather_kernel<<<ggrid, 256>>>(x, tgt);
    ctc_kernel<<<TB, NTH>>>(tgt, tmask, out);
}

// round 9
// speedup vs baseline: 1.3169x; 1.1614x over previous
#include <cuda_runtime.h>
#include <cstdint>
#include <math.h>

#define TB 64
#define TT 2048
#define TC 96
#define TS 256
#define NEGF (-1e30f)
#define LOG2E 1.4426950408889634f
#define LN2   0.6931471805599453f

#define GST 260            // floats per gathered row (257 used, 1040B = 65*16)
#define NTH 128            // 4 warps; thread i owns states 4i..4i+3; t127 also 512
#define RCH 5              // ring chunks of 8 rows (5*8*260*4 = 41600 B)
#define NCHK (TT / 8)

// G[b][t][j] = log2 p(lab_j | t) for j<256; G[..][256] = log2 p(blank | t)
__device__ __align__(16) float g_gather[(size_t)TB * TT * GST];

__device__ __forceinline__ float ex2f_(float x) {
    float r; asm("ex2.approx.f32 %0, %1;" : "=f"(r) : "f"(x)); return r;
}
__device__ __forceinline__ float lg2f_(float x) {
    float r; asm("lg2.approx.f32 %0, %1;" : "=f"(r) : "f"(x)); return r;
}
__device__ __forceinline__ float lse2f_(float a, float b) {
    float m = fmaxf(a, b), n = fminf(a, b);
    return m + lg2f_(1.0f + ex2f_(n - m));
}
__device__ __forceinline__ float lse3f_(float a, float b, float c) {
    float s1 = fmaxf(a, b), t1 = fminf(a, b);
    float m  = fmaxf(s1, c);
    float md = fmaxf(fminf(s1, c), t1);
    float mn = fminf(t1, c);
    return m + lg2f_(1.0f + ex2f_(md - m) + ex2f_(mn - m));
}

__global__ void zero_kernel(float* o) { if (threadIdx.x == 0) *o = 0.0f; }

// ---------------------------------------------------------------------------
// Gather: precise log-softmax + per-state class gather into log2 domain.
// 256 threads = 8 warps, one warp per t-row; grid (TT/8, TB).
// ---------------------------------------------------------------------------
__global__ void __launch_bounds__(256) gather_kernel(
    const float* __restrict__ x, const int* __restrict__ tgt32)
{
    __shared__ int   lab[TS];
    __shared__ float raw[8][TC];

    const int tid = threadIdx.x, lane = tid & 31, r = tid >> 5;
    const int b = blockIdx.y, t0 = blockIdx.x * 8;

    const bool is64 = (tgt32[1] == 0);          // labels>=1 => hi word 0 iff i64 LE
    const int  stride = is64 ? 2 : 1;
    lab[tid] = tgt32[((size_t)b * TS + tid) * stride];

    const float* xr = x + ((size_t)b * TT + t0 + r) * TC;
    float v0 = xr[lane], v1 = xr[lane + 32], v2 = xr[lane + 64];
    raw[r][lane] = v0; raw[r][lane + 32] = v1; raw[r][lane + 64] = v2;
    float m = fmaxf(fmaxf(v0, v1), v2);
    #pragma unroll
    for (int o = 16; o; o >>= 1) m = fmaxf(m, __shfl_xor_sync(0xffffffffu, m, o));
    float s = expf(v0 - m) + expf(v1 - m) + expf(v2 - m);   // precise
    #pragma unroll
    for (int o = 16; o; o >>= 1) s += __shfl_xor_sync(0xffffffffu, s, o);
    float lse2 = fmaf(m, LOG2E, log2f(s));                  // precise
    __syncthreads();

    float* Gr = g_gather + ((size_t)b * TT + t0 + r) * GST;
    #pragma unroll
    for (int j = lane; j < TS; j += 32)
        Gr[j] = fmaf(raw[r][lab[j]], LOG2E, -lse2);
    if (lane == 0) Gr[256] = fmaf(raw[r][0], LOG2E, -lse2);
}

// ---------------------------------------------------------------------------
// Main kernel: one CTA per batch; 2-step trapezoid rounds, 1 barrier / 2 steps.
// ---------------------------------------------------------------------------
__global__ void __launch_bounds__(NTH, 1) ctc_kernel(
    const int* __restrict__ tgt32,
    const int* __restrict__ tmask,
    float*     __restrict__ out)
{
    __shared__ __align__(16) float ring[RCH][8 * GST];
    __shared__ float shOB[2][4][4];    // [parity][warp][c3,b2,c1,pad]
    __shared__ __align__(16) float fin[516];
    __shared__ int   tlen_sh;

    const int tid = threadIdx.x, lane = tid & 31, w = tid >> 5;
    const int b = blockIdx.x, i = tid;

    const bool is64 = (tgt32[1] == 0);
    const int  stride = is64 ? 2 : 1;
    const int* trow = tgt32 + (size_t)b * TS * stride;

    // labels around this thread's states 4i..4i+3 (labels 2i, 2i+1)
    int l2i   = trow[(2 * i) * stride];
    int l2i1  = trow[(2 * i + 1) * stride];
    int l2im1 = (i > 0) ? trow[(2 * i - 1) * stride] : -1;
    int l2im2 = (i > 0) ? trow[(2 * i - 2) * stride] : -1;
    const bool sk0 = (i > 0) && (l2i  != l2im1);   // state 4i+1 skip
    const bool sk1 = (l2i1 != l2i);                // state 4i+3 skip
    const bool skL = (i > 0) && (l2im1 != l2im2);  // ghost state 4i-1 skip

    if (tid < 32) ((float*)shOB)[tid] = NEGF;      // 2*4*4 = 32 floats
    if (w == 0) {
        int s = 0;
        #pragma unroll
        for (int k = lane; k < TS; k += 32) s += tmask[b * TS + k];
        #pragma unroll
        for (int o = 16; o; o >>= 1) s += __shfl_xor_sync(0xffffffffu, s, o);
        if (lane == 0) tlen_sh = s;
    }

    const float* Gb = g_gather + (size_t)b * TT * GST;

    // one chunk = 8 rows = 2080 floats = 520 x 16B, contiguous
    auto issue_chunk = [&](int c) {
        if (c < NCHK) {
            unsigned sa = (unsigned)__cvta_generic_to_shared(ring[c % RCH]);
            const float* src = Gb + (size_t)c * (8 * GST);
            #pragma unroll
            for (int k = tid; k < 520; k += NTH)
                asm volatile("cp.async.ca.shared.global [%0], [%1], 16;"
                             :: "r"(sa + k * 16), "l"(src + k * 4));
        }
        asm volatile("cp.async.commit_group;");
    };

    issue_chunk(0); issue_chunk(1); issue_chunk(2); issue_chunk(3);
    asm volatile("cp.async.wait_group 3;");        // chunk 0 complete
    __syncthreads();

    // alphas in registers: b0=a[4i] c1=a[4i+1] b2=a[4i+2] c3=a[4i+3]
    float b0 = NEGF, c1 = NEGF, b2 = NEGF, c3 = NEGF, aX = NEGF;

    // ---- t = 0 peel ----
    {
        const float* R = ring[0];
        if (i == 0) { b0 = R[256]; c1 = R[0]; }
        if (lane == 31) { shOB[0][w][0] = c3; shOB[0][w][1] = b2; shOB[0][w][2] = c1; }
    }
    int pb = 0;

    // ---- rounds: steps (2r+1, 2r+2), r = 0..1022 ----
    for (int r = 0; r < 1023; ++r) {
        const int t1 = 2 * r + 1;
        if ((t1 & 7) == 7) {                       // chunk event (every 4 rounds)
            asm volatile("cp.async.wait_group 2;");
            __syncthreads();
            issue_chunk((t1 >> 3) + 1 + 3);        // chunk c+3
        } else {
            __syncthreads();
        }

        const float* R1 = ring[(t1 >> 3) % RCH] + (t1 & 7) * GST;
        const float* R2 = ring[((t1 + 1) >> 3) % RCH] + ((t1 + 1) & 7) * GST;

        // left-neighbor alphas at round-start time
        float c3L = __shfl_up_sync(0xffffffffu, c3, 1);
        float b2L = __shfl_up_sync(0xffffffffu, b2, 1);
        float c1L = __shfl_up_sync(0xffffffffu, c1, 1);
        if (lane == 0) {
            if (w) { c3L = shOB[pb][w-1][0]; b2L = shOB[pb][w-1][1]; c1L = shOB[pb][w-1][2]; }
            else   { c3L = NEGF; b2L = NEGF; c1L = NEGF; }
        }

        // ---- step 1 (row t1) ----
        float2 lpa = *(const float2*)(R1 + 2 * i);
        float  lpm = R1[(i > 0) ? (2 * i - 1) : 0];
        float  pB1 = R1[256];
        float g3 = lse3f_(c3L, b2L, skL ? c1L : NEGF) + lpm;     // ghost state 4i-1
        float n0 = lse2f_(b0, c3L) + pB1;
        float n1 = lse3f_(c1, b0, sk0 ? c3L : NEGF) + lpa.x;
        float n2 = lse2f_(b2, c1) + pB1;
        float n3 = lse3f_(c3, b2, sk1 ? c1 : NEGF) + lpa.y;
        float aX1 = (i == NTH - 1) ? (lse2f_(aX, c3) + pB1) : aX;

        // ---- step 2 (row t1+1) ----
        float2 lpb = *(const float2*)(R2 + 2 * i);
        float  pB2 = R2[256];
        b0 = lse2f_(n0, g3) + pB2;
        c1 = lse3f_(n1, n0, sk0 ? g3 : NEGF) + lpb.x;
        b2 = lse2f_(n2, n1) + pB2;
        c3 = lse3f_(n3, n2, sk1 ? n1 : NEGF) + lpb.y;
        aX = (i == NTH - 1) ? (lse2f_(aX1, n3) + pB2) : aX1;

        if (lane == 31) {
            shOB[pb ^ 1][w][0] = c3; shOB[pb ^ 1][w][1] = b2; shOB[pb ^ 1][w][2] = c1;
        }
        pb ^= 1;
    }

    // ---- tail step t = 2047 ----
    __syncthreads();
    {
        const float* R = ring[(2047 >> 3) % RCH] + (2047 & 7) * GST;
        float c3L = __shfl_up_sync(0xffffffffu, c3, 1);
        if (lane == 0) c3L = w ? shOB[pb][w-1][0] : NEGF;
        float2 lp = *(const float2*)(R + 2 * i);
        float  pB = R[256];
        float n0 = lse2f_(b0, c3L) + pB;
        float n1 = lse3f_(c1, b0, sk0 ? c3L : NEGF) + lp.x;
        float n2 = lse2f_(b2, c1) + pB;
        float n3 = lse3f_(c3, b2, sk1 ? c1 : NEGF) + lp.y;
        if (i == NTH - 1) aX = lse2f_(aX, c3) + pB;
        b0 = n0; c1 = n1; b2 = n2; c3 = n3;
    }

    *(float4*)(fin + 4 * i) = make_float4(b0, c1, b2, c3);
    if (i == NTH - 1) fin[512] = aX;
    __syncthreads();

    if (tid == 0) {
        int len = tlen_sh;
        float loss = 0.0f;
        if (len >= 1 && len <= TS) {
            float la = lse2f_(fin[2 * len], fin[2 * len - 1]);
            float l  = -la * LN2;
            if (isfinite(l) && l < 1e29f)
                loss = l / ((float)len * (float)TB);
        }
        atomicAdd(out, loss);
    }
}

// ---------------------------------------------------------------------------
extern "C" void kernel_launch(void* const* d_in, const int* in_sizes, int n_in,
                              void* d_out, int out_size) {
    const float* x     = (const float*)d_in[0];   // predictions [B,T,C] f32
    const int*   tgt   = (const int*)  d_in[1];   // targets (int32 or int64 words)
    const int*   tmask = (const int*)  d_in[3];   // targets_mask [B,S] i32
    float* out = (float*)d_out;

    zero_kernel<<<1, 32>>>(out);
    dim3 ggrid(TT / 8, TB);
    gather_kernel<<<ggrid, 256>>>(x, tgt);
    ctc_kernel<<<TB, NTH>>>(tgt, tmask, out);
}